// round 3
// baseline (speedup 1.0000x reference)
#include <cuda_runtime.h>

#define TT 2048
#define DD 64
#define HH 64
#define NG 256   // 4*H gates
#define BB_TOT 256

// 512 MB scratch: precomputed input projections xg[b][t][g] (bias included)
__device__ float g_xg[(size_t)BB_TOT * TT * NG];

// Packed fp32x2 FMA (sm_100+): d = a*b + c on two packed floats.
__device__ __forceinline__ unsigned long long ffma2(unsigned long long a,
                                                    unsigned long long b,
                                                    unsigned long long c) {
    unsigned long long d;
    asm("fma.rn.f32x2 %0, %1, %2, %3;" : "=l"(d) : "l"(a), "l"(b), "l"(c));
    return d;
}

__device__ __forceinline__ float red2(unsigned long long v) {
    float lo, hi;
    asm("mov.b64 {%0, %1}, %2;" : "=f"(lo), "=f"(hi) : "l"(v));
    return lo + hi;
}

__device__ __forceinline__ float sigm(float v) {
    return __fdividef(1.f, 1.f + __expf(-v));
}
__device__ __forceinline__ float tanh_(float v) {
    return 1.f - __fdividef(2.f, 1.f + __expf(2.f * v));
}

// ---------------------------------------------------------------------------
// Kernel 1: xg[row][g] = bias[g] + W_ih[g] . x[row]   for all B*T rows.
// 256 threads = 128 gate-pairs x 2 row-halves; each thread computes 2 gates
// (g, g+128) for 16 rows, sharing every x LDS between both gates.
// ---------------------------------------------------------------------------
__global__ void __launch_bounds__(256, 2)
xg_gemm(const float* __restrict__ x, const float* __restrict__ w_ih,
        const float* __restrict__ b_ih, const float* __restrict__ b_hh,
        int nrows)
{
    __shared__ __align__(16) float xs[32][DD];   // 32-row x tile (8 KB)

    const int tid  = threadIdx.x;
    const int tg   = tid & 127;       // gate pair: gates tg and tg+128
    const int half = tid >> 7;        // row group: 0 -> rows 0..15, 1 -> 16..31

    ulonglong2 wa[16], wb[16];
    {
        const ulonglong2* pa = (const ulonglong2*)(w_ih + tg * DD);
        const ulonglong2* pb = (const ulonglong2*)(w_ih + (tg + 128) * DD);
#pragma unroll
        for (int j = 0; j < 16; ++j) { wa[j] = pa[j]; wb[j] = pb[j]; }
    }
    const float ba = b_ih[tg] + b_hh[tg];
    const float bb = b_ih[tg + 128] + b_hh[tg + 128];

    const int ntiles = nrows / 32;
    for (int tile = blockIdx.x; tile < ntiles; tile += gridDim.x) {
        const float4* src = (const float4*)(x + (size_t)tile * 32 * DD);
        ((float4*)xs)[tid] = src[tid];
        ((float4*)xs)[tid + 256] = src[tid + 256];
        __syncthreads();

        float* dst = g_xg + ((size_t)tile * 32 + half * 16) * NG;
#pragma unroll 2
        for (int r = 0; r < 16; ++r) {
            const ulonglong2* v = (const ulonglong2*)xs[half * 16 + r];
            unsigned long long a0 = 0ull, a1 = 0ull, c0 = 0ull, c1 = 0ull;
#pragma unroll
            for (int j = 0; j < 16; ++j) {
                ulonglong2 h2 = v[j];
                a0 = ffma2(wa[j].x, h2.x, a0);
                a1 = ffma2(wa[j].y, h2.y, a1);
                c0 = ffma2(wb[j].x, h2.x, c0);
                c1 = ffma2(wb[j].y, h2.y, c1);
            }
            dst[r * NG + tg]       = ba + red2(a0) + red2(a1);
            dst[r * NG + tg + 128] = bb + red2(c0) + red2(c1);
        }
        __syncthreads();
    }
}

// ---------------------------------------------------------------------------
// Kernel 2: recurrence. 256 blocks (1 batch each) x 128 threads, 2 blocks/SM.
// Thread t owns gates t and t+128 (register-resident W_hh rows), sharing each
// h LDS between both gates. xg prefetched at distance 4.
// ---------------------------------------------------------------------------
__global__ void __launch_bounds__(128, 2)
lstm_rec(const float* __restrict__ w_hh, const float* __restrict__ fc_w,
         const float* __restrict__ fc_b, float* __restrict__ out, int Tn)
{
    __shared__ __align__(16) float hsm[HH];
    __shared__ __align__(16) float gact[NG];

    const int t  = threadIdx.x;     // 0..127
    const int b  = blockIdx.x;
    const int ga = t;               // i (t<64) or f (t>=64) gate
    const int gb = t + 128;         // g (t<64) or o (t>=64) gate

    ulonglong2 wa[16], wb[16];
    {
        const ulonglong2* pa = (const ulonglong2*)(w_hh + ga * HH);
        const ulonglong2* pb = (const ulonglong2*)(w_hh + gb * HH);
#pragma unroll
        for (int j = 0; j < 16; ++j) { wa[j] = pa[j]; wb[j] = pb[j]; }
    }

    const float* xpa = g_xg + (size_t)b * Tn * NG + ga;
    const float* xpb = xpa + 128;

    // prefetch pipeline, distance 4
    float ra  = xpa[0],      rb  = xpb[0];
    float f1a = xpa[NG],     f1b = xpb[NG];
    float f2a = xpa[2 * NG], f2b = xpb[2 * NG];
    float f3a = xpa[3 * NG], f3b = xpb[3 * NG];
    xpa += 4 * NG; xpb += 4 * NG;

    if (t < 64) hsm[t] = 0.f;
    __syncthreads();

    const bool b_is_tanh = (t < 64);   // warp-uniform: warps 0,1
    float cc = 0.f;

    for (int tt = 0; tt < Tn; ++tt) {
        const ulonglong2* hv = (const ulonglong2*)hsm;
        unsigned long long a0 = 0ull, a1 = 0ull, c0 = 0ull, c1 = 0ull;
#pragma unroll
        for (int j = 0; j < 16; ++j) {
            ulonglong2 h2 = hv[j];
            a0 = ffma2(wa[j].x, h2.x, a0);
            a1 = ffma2(wa[j].y, h2.y, a1);
            c0 = ffma2(wb[j].x, h2.x, c0);
            c1 = ffma2(wb[j].y, h2.y, c1);
        }
        float sa = ra + red2(a0) + red2(a1);
        float sb = rb + red2(c0) + red2(c1);

        // rotate prefetch; next LDG issued here overlaps activation + phase 2
        ra = f1a; f1a = f2a; f2a = f3a;
        rb = f1b; f1b = f2b; f2b = f3b;
        if (tt + 4 < Tn) {
            f3a = *xpa; f3b = *xpb;
            xpa += NG;  xpb += NG;
        }

        float aa = sigm(sa);
        float ab = b_is_tanh ? tanh_(sb) : sigm(sb);
        gact[ga] = aa;
        gact[gb] = ab;
        __syncthreads();

        if (t < 64) {
            float gi = gact[t];
            float gf = gact[64 + t];
            float gg = gact[128 + t];
            float go = gact[192 + t];
            cc = gf * cc + gi * gg;
            hsm[t] = go * tanh_(cc);
        }
        __syncthreads();
    }

    // final FC: out[b, o] = h_last . fc_w[o] + fc_b[o]
    if (t < 8) {
        float s = fc_b[t];
#pragma unroll
        for (int k = 0; k < HH; ++k) s += hsm[k] * fc_w[t * HH + k];
        out[b * 8 + t] = s;
    }
}

extern "C" void kernel_launch(void* const* d_in, const int* in_sizes, int n_in,
                              void* d_out, int out_size) {
    const float* x    = (const float*)d_in[0];
    const float* w_ih = (const float*)d_in[1];
    const float* w_hh = (const float*)d_in[2];
    const float* b_ih = (const float*)d_in[3];
    const float* b_hh = (const float*)d_in[4];
    const float* fc_w = (const float*)d_in[5];
    const float* fc_b = (const float*)d_in[6];
    float* out = (float*)d_out;

    const int B = in_sizes[0] / (TT * DD);   // 256
    const int nrows = B * TT;

    xg_gemm<<<296, 256>>>(x, w_ih, b_ih, b_hh, nrows);
    lstm_rec<<<B, 128>>>(w_hh, fc_w, fc_b, out, TT);
}

// round 5
// speedup vs baseline: 1.2253x; 1.2253x over previous
#include <cuda_runtime.h>

#define TT 2048
#define DD 64
#define HH 64
#define NG 256   // 4*H gates
#define BB_TOT 256

// 512 MB scratch: precomputed input projections xg[b][t][g] (bias included)
__device__ float g_xg[(size_t)BB_TOT * TT * NG];

// Packed fp32x2 FMA (sm_100+): d = a*b + c on two packed floats.
__device__ __forceinline__ unsigned long long ffma2(unsigned long long a,
                                                    unsigned long long b,
                                                    unsigned long long c) {
    unsigned long long d;
    asm("fma.rn.f32x2 %0, %1, %2, %3;" : "=l"(d) : "l"(a), "l"(b), "l"(c));
    return d;
}

__device__ __forceinline__ float red2(unsigned long long v) {
    float lo, hi;
    asm("mov.b64 {%0, %1}, %2;" : "=f"(lo), "=f"(hi) : "l"(v));
    return lo + hi;
}

// 64-element dot: w in registers, v in shared (broadcast LDS.128)
__device__ __forceinline__ float dot64(const ulonglong2* __restrict__ w,
                                       const ulonglong2* v) {
    unsigned long long a0 = 0ull, a1 = 0ull;
#pragma unroll
    for (int j = 0; j < 16; ++j) {
        ulonglong2 h2 = v[j];
        a0 = ffma2(w[j].x, h2.x, a0);
        a1 = ffma2(w[j].y, h2.y, a1);
    }
    return red2(a0) + red2(a1);
}

__device__ __forceinline__ float sigm(float v) {
    return __fdividef(1.f, 1.f + __expf(-v));
}
__device__ __forceinline__ float tanh_(float v) {
    return 1.f - __fdividef(2.f, 1.f + __expf(2.f * v));
}

// ---------------------------------------------------------------------------
// Kernel 1 (identical to R2, known 520us): xg[row][g] = bias[g] + W_ih[g].x[row]
// ---------------------------------------------------------------------------
__global__ void __launch_bounds__(256, 2)
xg_gemm(const float* __restrict__ x, const float* __restrict__ w_ih,
        const float* __restrict__ b_ih, const float* __restrict__ b_hh,
        int nrows)
{
    __shared__ __align__(16) float xs[32][DD];

    const int tid = threadIdx.x;
    ulonglong2 w[16];
    {
        const ulonglong2* wp = (const ulonglong2*)(w_ih + tid * DD);
#pragma unroll
        for (int j = 0; j < 16; ++j) w[j] = wp[j];
    }
    const float bias = b_ih[tid] + b_hh[tid];

    const int ntiles = nrows / 32;
    for (int tile = blockIdx.x; tile < ntiles; tile += gridDim.x) {
        const float4* src = (const float4*)(x + (size_t)tile * 32 * DD);
#pragma unroll
        for (int i = 0; i < 2; ++i) {
            int s = tid * 2 + i;
            ((float4*)xs)[s] = src[s];
        }
        __syncthreads();

        float* dst = g_xg + (size_t)tile * 32 * NG + tid;
#pragma unroll 4
        for (int r = 0; r < 32; ++r) {
            dst[r * NG] = bias + dot64(w, (const ulonglong2*)xs[r]);
        }
        __syncthreads();
    }
}

// ---------------------------------------------------------------------------
// Kernel 2: recurrence. grid=128, 256 threads = 2 independent 128-thread
// groups (one batch each, own named barrier). Thread pair (lane, lane^1):
// role0 owns gates (i_u, g_u), role1 (f_u, o_u). Cell update via 2x shfl.xor.
// h is DOUBLE-BUFFERED so one barrier per step is race-free:
//   read hsm[grp][t&1], write hsm[grp][(t+1)&1].
// ---------------------------------------------------------------------------
__global__ void __launch_bounds__(256, 1)
lstm_rec(const float* __restrict__ w_hh, const float* __restrict__ fc_w,
         const float* __restrict__ fc_b, float* __restrict__ out, int Tn)
{
    __shared__ __align__(16) float hsm[2][2][HH];   // [grp][buf][unit]

    const int tid  = threadIdx.x;
    const int grp  = tid >> 7;          // group = batch within block
    const int lt   = tid & 127;
    const int u    = lt >> 1;           // unit 0..63
    const int role = lt & 1;            // 0: (i,g)   1: (f,o)
    const int ga   = u + 64 * role;     // i_u or f_u
    const int gb   = ga + 128;          // g_u or o_u
    const int b    = blockIdx.x * 2 + grp;
    const int barid = grp + 1;

    ulonglong2 wa[16], wb[16];
    {
        const ulonglong2* pwa = (const ulonglong2*)(w_hh + ga * HH);
        const ulonglong2* pwb = (const ulonglong2*)(w_hh + gb * HH);
#pragma unroll
        for (int j = 0; j < 16; ++j) { wa[j] = pwa[j]; wb[j] = pwb[j]; }
    }

    // activation constants: role0 gb is tanh; everything else sigmoid
    const float kk = role ? 1.f : 2.f;     // exp scale for gb activation
    const float mm = role ? 1.f : 2.f;     // numerator
    const float ad = role ? 0.f : -1.f;    // additive term

    const float* pa = g_xg + (size_t)b * Tn * NG + ga;
    const float* pb = pa + 128;

    // prefetch pipeline, distance 4
    float xa0 = pa[0],      xb0 = pb[0];
    float xa1 = pa[NG],     xb1 = pb[NG];
    float xa2 = pa[2 * NG], xb2 = pb[2 * NG];
    float xa3 = pa[3 * NG], xb3 = pb[3 * NG];
    pa += 4 * NG; pb += 4 * NG;

    if (lt < 64) { hsm[grp][0][lt] = 0.f; hsm[grp][1][lt] = 0.f; }
    __syncthreads();

    float c = 0.f;   // cell state lives on role0 threads

    for (int t = 0; t < Tn; ++t) {
        const ulonglong2* hv = (const ulonglong2*)hsm[grp][t & 1];
        unsigned long long a0 = 0ull, a1 = 0ull, c0 = 0ull, c1 = 0ull;
#pragma unroll
        for (int j = 0; j < 16; ++j) {
            ulonglong2 h2 = hv[j];
            a0 = ffma2(wa[j].x, h2.x, a0);
            a1 = ffma2(wa[j].y, h2.y, a1);
            c0 = ffma2(wb[j].x, h2.x, c0);
            c1 = ffma2(wb[j].y, h2.y, c1);
        }
        float sa = xa0 + red2(a0) + red2(a1);
        float sb = xb0 + red2(c0) + red2(c1);

        // rotate prefetch; LDG overlaps the epilogue
        xa0 = xa1; xa1 = xa2; xa2 = xa3;
        xb0 = xb1; xb1 = xb2; xb2 = xb3;
        if (t + 4 < Tn) {
            xa3 = *pa; xb3 = *pb;
            pa += NG;  pb += NG;
        }

        // activations (branch-free; role decides tanh vs sigmoid for sb)
        float A  = sigm(sa);                                    // i or f
        float Bv = __fdividef(mm, 1.f + __expf(-kk * sb)) + ad; // g or o
        float p  = A * Bv;                                      // role0: i*g
        float fx = __shfl_xor_sync(0xFFFFFFFFu, A, 1);          // role0 gets f
        c = fx * c + p;                                         // valid on role0
        float tc = tanh_(c);
        float tcx = __shfl_xor_sync(0xFFFFFFFFu, tc, 1);        // role1 gets tc
        if (role) hsm[grp][(t + 1) & 1][u] = Bv * tcx;          // h = o*tanh(c)

        asm volatile("bar.sync %0, 128;" :: "r"(barid));
    }

    // final FC: out[b, o] = h_last . fc_w[o] + fc_b[o]
    const float* hfin = hsm[grp][Tn & 1];
    if (lt < 8) {
        float s = fc_b[lt];
#pragma unroll
        for (int k = 0; k < HH; ++k) s += hfin[k] * fc_w[lt * HH + k];
        out[b * 8 + lt] = s;
    }
}

extern "C" void kernel_launch(void* const* d_in, const int* in_sizes, int n_in,
                              void* d_out, int out_size) {
    const float* x    = (const float*)d_in[0];
    const float* w_ih = (const float*)d_in[1];
    const float* w_hh = (const float*)d_in[2];
    const float* b_ih = (const float*)d_in[3];
    const float* b_hh = (const float*)d_in[4];
    const float* fc_w = (const float*)d_in[5];
    const float* fc_b = (const float*)d_in[6];
    float* out = (float*)d_out;

    const int B = in_sizes[0] / (TT * DD);   // 256
    const int nrows = B * TT;

    xg_gemm<<<296, 256>>>(x, w_ih, b_ih, b_hh, nrows);
    lstm_rec<<<B / 2, 256>>>(w_hh, fc_w, fc_b, out, TT);
}

// round 6
// speedup vs baseline: 1.4477x; 1.1815x over previous
#include <cuda_runtime.h>

#define TT 2048
#define DD 64
#define HH 64
#define NG 256   // 4*H gates
#define BB_TOT 256

// 512 MB scratch: precomputed input projections xg[b][t][g] (bias included)
__device__ float g_xg[(size_t)BB_TOT * TT * NG];

// Packed fp32x2 FMA (sm_100+): d = a*b + c on two packed floats.
__device__ __forceinline__ unsigned long long ffma2(unsigned long long a,
                                                    unsigned long long b,
                                                    unsigned long long c) {
    unsigned long long d;
    asm("fma.rn.f32x2 %0, %1, %2, %3;" : "=l"(d) : "l"(a), "l"(b), "l"(c));
    return d;
}

__device__ __forceinline__ float red2(unsigned long long v) {
    float lo, hi;
    asm("mov.b64 {%0, %1}, %2;" : "=f"(lo), "=f"(hi) : "l"(v));
    return lo + hi;
}

// HW tanh: single MUFU op (sm_75+), ~16 cyc, abs err ~1e-5
__device__ __forceinline__ float tanh_ap(float x) {
    float y;
    asm("tanh.approx.f32 %0, %1;" : "=f"(y) : "f"(x));
    return y;
}

// ---------------------------------------------------------------------------
// Kernel 1: xg[row][g] = bias[g] + W_ih[g].x[row].
// 256 threads = 128 gate-pairs (adjacent gates 2tg, 2tg+1) x 2 row-halves.
// 2 gates/thread halves LDS per MAC; grid=148 (1 block/SM, even);
// double-buffered x tile with register prefetch overlaps LDG with compute.
// ---------------------------------------------------------------------------
__global__ void __launch_bounds__(256, 1)
xg_gemm(const float* __restrict__ x, const float* __restrict__ w_ih,
        const float* __restrict__ b_ih, const float* __restrict__ b_hh,
        int nrows)
{
    __shared__ __align__(16) float xs[2][32][DD];   // 2 x 8KB tiles

    const int tid  = threadIdx.x;
    const int tg   = tid & 127;       // gate pair: gates 2tg, 2tg+1
    const int half = tid >> 7;        // rows 0..15 or 16..31
    const int g0   = 2 * tg;

    ulonglong2 wa[16], wb[16];
    {
        const ulonglong2* pa = (const ulonglong2*)(w_ih + (size_t)g0 * DD);
        const ulonglong2* pb = (const ulonglong2*)(w_ih + (size_t)(g0 + 1) * DD);
#pragma unroll
        for (int j = 0; j < 16; ++j) { wa[j] = pa[j]; wb[j] = pb[j]; }
    }
    const float ba = b_ih[g0] + b_hh[g0];
    const float bb = b_ih[g0 + 1] + b_hh[g0 + 1];

    const int ntiles = nrows / 32;
    int tile = blockIdx.x;
    int buf = 0;

    float4 pre0 = make_float4(0.f, 0.f, 0.f, 0.f), pre1 = pre0;
    if (tile < ntiles) {
        const float4* src = (const float4*)(x + (size_t)tile * 32 * DD);
        pre0 = src[tid]; pre1 = src[tid + 256];
    }

    while (tile < ntiles) {
        ((float4*)xs[buf])[tid] = pre0;
        ((float4*)xs[buf])[tid + 256] = pre1;
        __syncthreads();

        int next = tile + gridDim.x;
        if (next < ntiles) {   // prefetch next tile; LDG overlaps compute below
            const float4* src = (const float4*)(x + (size_t)next * 32 * DD);
            pre0 = src[tid]; pre1 = src[tid + 256];
        }

        float* dst = g_xg + ((size_t)tile * 32 + half * 16) * NG + g0;
#pragma unroll 2
        for (int r = 0; r < 16; ++r) {
            const ulonglong2* v = (const ulonglong2*)xs[buf][half * 16 + r];
            unsigned long long a0 = 0ull, a1 = 0ull, c0 = 0ull, c1 = 0ull;
#pragma unroll
            for (int j = 0; j < 16; ++j) {
                ulonglong2 h2 = v[j];
                a0 = ffma2(wa[j].x, h2.x, a0);
                a1 = ffma2(wa[j].y, h2.y, a1);
                c0 = ffma2(wb[j].x, h2.x, c0);
                c1 = ffma2(wb[j].y, h2.y, c1);
            }
            *(float2*)(dst + r * NG) =
                make_float2(ba + red2(a0) + red2(a1), bb + red2(c0) + red2(c1));
        }
        buf ^= 1;
        tile = next;
    }
}

// ---------------------------------------------------------------------------
// Kernel 2: recurrence. grid=128, 256 threads = 2 independent 128-thread
// groups (one batch each, own named barrier). Pair (lane, lane^1):
// role0 owns gates (i_u, g_u), role1 (f_u, o_u). Redundant cell state on
// both roles -> ONE shfl per step. All activations via MUFU tanh.approx.
// h double-buffered -> one barrier per step, race-free.
// ---------------------------------------------------------------------------
__global__ void __launch_bounds__(256, 1)
lstm_rec(const float* __restrict__ w_hh, const float* __restrict__ fc_w,
         const float* __restrict__ fc_b, float* __restrict__ out, int Tn)
{
    __shared__ __align__(16) float hsm[2][2][HH];   // [grp][buf][unit]

    const int tid  = threadIdx.x;
    const int grp  = tid >> 7;
    const int lt   = tid & 127;
    const int u    = lt >> 1;           // unit 0..63
    const int role = lt & 1;            // 0: (i,g)   1: (f,o)
    const int ga   = u + 64 * role;     // i_u or f_u
    const int gb   = ga + 128;          // g_u or o_u
    const int b    = blockIdx.x * 2 + grp;
    const int barid = grp + 1;

    ulonglong2 wa[16], wb[16];
    {
        const ulonglong2* pwa = (const ulonglong2*)(w_hh + ga * HH);
        const ulonglong2* pwb = (const ulonglong2*)(w_hh + gb * HH);
#pragma unroll
        for (int j = 0; j < 16; ++j) { wa[j] = pwa[j]; wb[j] = pwb[j]; }
    }

    // Bv activation: role0 -> tanh(sb); role1 -> sigm(sb)=0.5*tanh(0.5*sb)+0.5
    const float kb = role ? 0.5f : 1.f;
    const float sc = role ? 0.5f : 1.f;
    const float off = role ? 0.5f : 0.f;

    const float* pa = g_xg + (size_t)b * Tn * NG + ga;
    const float* pb = pa + 128;

    // prefetch pipeline, distance 4
    float xa0 = pa[0],      xb0 = pb[0];
    float xa1 = pa[NG],     xb1 = pb[NG];
    float xa2 = pa[2 * NG], xb2 = pb[2 * NG];
    float xa3 = pa[3 * NG], xb3 = pb[3 * NG];
    pa += 4 * NG; pb += 4 * NG;

    if (lt < 64) { hsm[grp][0][lt] = 0.f; hsm[grp][1][lt] = 0.f; }
    __syncthreads();

    float c = 0.f;   // redundant cell state on BOTH roles

    for (int t = 0; t < Tn; ++t) {
        const ulonglong2* hv = (const ulonglong2*)hsm[grp][t & 1];
        unsigned long long a0 = 0ull, a1 = 0ull, c0 = 0ull, c1 = 0ull;
#pragma unroll
        for (int j = 0; j < 16; ++j) {
            ulonglong2 h2 = hv[j];
            a0 = ffma2(wa[j].x, h2.x, a0);
            a1 = ffma2(wa[j].y, h2.y, a1);
            c0 = ffma2(wb[j].x, h2.x, c0);
            c1 = ffma2(wb[j].y, h2.y, c1);
        }
        float sa = xa0 + red2(a0) + red2(a1);
        float sb = xb0 + red2(c0) + red2(c1);

        // rotate prefetch; LDG overlaps the epilogue
        xa0 = xa1; xa1 = xa2; xa2 = xa3;
        xb0 = xb1; xb1 = xb2; xb2 = xb3;
        if (t + 4 < Tn) {
            xa3 = *pa; xb3 = *pb;
            pa += NG;  pb += NG;
        }

        // activations (MUFU tanh): A = sigmoid(sa) = i (role0) or f (role1)
        float A  = fmaf(0.5f, tanh_ap(0.5f * sa), 0.5f);
        float Bv = fmaf(sc, tanh_ap(kb * sb), off);   // g (role0) or o (role1)
        float p  = A * Bv;                            // role0: i*g
        float send = role ? A : p;                    // role1 sends f, role0 sends p
        float recv = __shfl_xor_sync(0xFFFFFFFFu, send, 1);
        float cmul = role ? A : recv;                 // f on both roles
        float cadd = role ? recv : p;                 // i*g on both roles
        c = fmaf(cmul, c, cadd);                      // identical on both roles
        float th = tanh_ap(c);
        if (role) hsm[grp][(t + 1) & 1][u] = Bv * th; // h = o * tanh(c)

        asm volatile("bar.sync %0, 128;" :: "r"(barid));
    }

    // final FC: out[b, o] = h_last . fc_w[o] + fc_b[o]
    const float* hfin = hsm[grp][Tn & 1];
    if (lt < 8) {
        float s = fc_b[lt];
#pragma unroll
        for (int k = 0; k < HH; ++k) s += hfin[k] * fc_w[lt * HH + k];
        out[b * 8 + lt] = s;
    }
}

extern "C" void kernel_launch(void* const* d_in, const int* in_sizes, int n_in,
                              void* d_out, int out_size) {
    const float* x    = (const float*)d_in[0];
    const float* w_ih = (const float*)d_in[1];
    const float* w_hh = (const float*)d_in[2];
    const float* b_ih = (const float*)d_in[3];
    const float* b_hh = (const float*)d_in[4];
    const float* fc_w = (const float*)d_in[5];
    const float* fc_b = (const float*)d_in[6];
    float* out = (float*)d_out;

    const int B = in_sizes[0] / (TT * DD);   // 256
    const int nrows = B * TT;

    xg_gemm<<<148, 256>>>(x, w_ih, b_ih, b_hh, nrows);
    lstm_rec<<<B / 2, 256>>>(w_hh, fc_w, fc_b, out, TT);
}